// round 12
// baseline (speedup 1.0000x reference)
#include <cuda_runtime.h>
#include <math.h>
#include <stdint.h>

// ---------------- scratch (device globals; no allocation allowed) ----------
#define TLEN 4096
__device__ float g_q[TLEN * 2048];
__device__ float g_k[TLEN * 512];
__device__ float g_v[TLEN * 512];
__device__ float g_att[TLEN * 2048];
__device__ float g_wcat[3072 * 2048];   // [wq;wk;wv] concatenated

__device__ __forceinline__ uint32_t f2tf(float x) {
    uint32_t r;
    asm("cvt.rna.tf32.f32 %0, %1;" : "=r"(r) : "f"(x));
    return r;
}
__device__ __forceinline__ void mma_tf32(float c[4], const uint32_t a[4],
                                         const uint32_t b0, const uint32_t b1) {
    asm volatile(
        "mma.sync.aligned.m16n8k8.row.col.f32.tf32.tf32.f32 "
        "{%0,%1,%2,%3},{%4,%5,%6,%7},{%8,%9},{%0,%1,%2,%3};\n"
        : "+f"(c[0]), "+f"(c[1]), "+f"(c[2]), "+f"(c[3])
        : "r"(a[0]), "r"(a[1]), "r"(a[2]), "r"(a[3]), "r"(b0), "r"(b1));
}

// ====== double-buffered TF32 GEMM: C[M,N] = A[M,K] * B[N,K]^T =============
// Tile 128x128x32, 256 thr = 8 warps, warp tile 64x32 (4x4 m16n8k8).
// Paired-k SMEM layout: within each 8-k group, k j and j+4 are adjacent
// (pos 2j / 2j+1) so every fragment fetch is one LDS.64. Row stride 40
// words -> read banks (8g+2t) mod 32, conflict-free per 16-lane phase.
#define GPAD 40
#define STGW 10240         // uint32 words per stage (2 * 128 * 40)
#define GEMM_SMEM 81920    // bytes (2 stages)

__global__ __launch_bounds__(256, 2) void gemm_db(
    const float* __restrict__ A, const float* __restrict__ B,
    float* __restrict__ c0, int nc0, int ld0,
    float* __restrict__ c1, int nc1, int ld1,
    float* __restrict__ c2, int ld2, int K)
{
    extern __shared__ uint32_t sm[];

    const int tid  = threadIdx.x;
    const int warp = tid >> 5;
    const int lane = tid & 31;
    const int gid  = lane >> 2;
    const int tig  = lane & 3;
    const int wm   = (warp >> 2) * 64;
    const int wn   = (warp & 3) * 32;
    const int m0   = blockIdx.y * 128;
    const int n0   = blockIdx.x * 128;

    const int lr = tid >> 3;                        // 0..31
    const int lk = (tid & 7) * 4;                   // 0..28 (4 consecutive k)
    // permuted store base: group*8 + parity; values go to base + 2*i
    const int sp = (lk >> 3) * 8 + ((lk >> 2) & 1);

    float acc[4][4][4];
#pragma unroll
    for (int mi = 0; mi < 4; mi++)
#pragma unroll
        for (int ni = 0; ni < 4; ni++)
#pragma unroll
            for (int r = 0; r < 4; r++) acc[mi][ni][r] = 0.0f;

    const float* Ap = A + (size_t)(m0 + lr) * K + lk;
    const float* Bp = B + (size_t)(n0 + lr) * K + lk;
    const int NT = K >> 5;

    // prologue: tile 0 -> stage 0
    {
        float4 ra[4], rb[4];
#pragma unroll
        for (int i = 0; i < 4; i++) {
            ra[i] = *(const float4*)(Ap + (size_t)i * 32 * K);
            rb[i] = *(const float4*)(Bp + (size_t)i * 32 * K);
        }
        uint32_t* As = sm;
        uint32_t* Bs = sm + 5120;
#pragma unroll
        for (int i = 0; i < 4; i++) {
            uint32_t* as = &As[(lr + i * 32) * GPAD + sp];
            as[0] = f2tf(ra[i].x); as[2] = f2tf(ra[i].y);
            as[4] = f2tf(ra[i].z); as[6] = f2tf(ra[i].w);
            uint32_t* bs = &Bs[(lr + i * 32) * GPAD + sp];
            bs[0] = f2tf(rb[i].x); bs[2] = f2tf(rb[i].y);
            bs[4] = f2tf(rb[i].z); bs[6] = f2tf(rb[i].w);
        }
    }
    __syncthreads();

    for (int kt = 0; kt < NT; kt++) {
        uint32_t* As = sm + (kt & 1) * STGW;
        uint32_t* Bs = As + 5120;
        uint32_t* Asn = sm + ((kt + 1) & 1) * STGW;
        uint32_t* Bsn = Asn + 5120;
        const bool more = (kt + 1 < NT);

        float4 ra[4];
        if (more) {
            const float* Apn = Ap + (kt + 1) * 32;
#pragma unroll
            for (int i = 0; i < 4; i++)
                ra[i] = *(const float4*)(Apn + (size_t)i * 32 * K);
        }

        // ks 0,1
#pragma unroll
        for (int ks = 0; ks < 2; ks++) {
            const int kk = ks * 8 + 2 * tig;
            uint32_t af[4][4];
#pragma unroll
            for (int mi = 0; mi < 4; mi++) {
                const int r0 = wm + mi * 16 + gid;
                uint2 lo = *(const uint2*)&As[(r0    ) * GPAD + kk];
                uint2 hi = *(const uint2*)&As[(r0 + 8) * GPAD + kk];
                af[mi][0] = lo.x; af[mi][1] = hi.x;
                af[mi][2] = lo.y; af[mi][3] = hi.y;
            }
#pragma unroll
            for (int ni = 0; ni < 4; ni++) {
                const int c0i = wn + ni * 8 + gid;
                uint2 bb = *(const uint2*)&Bs[c0i * GPAD + kk];
#pragma unroll
                for (int mi = 0; mi < 4; mi++)
                    mma_tf32(acc[mi][ni], af[mi], bb.x, bb.y);
            }
        }

        float4 rb[4];
        if (more) {
#pragma unroll
            for (int i = 0; i < 4; i++) {
                uint32_t* as = &Asn[(lr + i * 32) * GPAD + sp];
                as[0] = f2tf(ra[i].x); as[2] = f2tf(ra[i].y);
                as[4] = f2tf(ra[i].z); as[6] = f2tf(ra[i].w);
            }
            const float* Bpn = Bp + (kt + 1) * 32;
#pragma unroll
            for (int i = 0; i < 4; i++)
                rb[i] = *(const float4*)(Bpn + (size_t)i * 32 * K);
        }

        // ks 2,3
#pragma unroll
        for (int ks = 2; ks < 4; ks++) {
            const int kk = ks * 8 + 2 * tig;
            uint32_t af[4][4];
#pragma unroll
            for (int mi = 0; mi < 4; mi++) {
                const int r0 = wm + mi * 16 + gid;
                uint2 lo = *(const uint2*)&As[(r0    ) * GPAD + kk];
                uint2 hi = *(const uint2*)&As[(r0 + 8) * GPAD + kk];
                af[mi][0] = lo.x; af[mi][1] = hi.x;
                af[mi][2] = lo.y; af[mi][3] = hi.y;
            }
#pragma unroll
            for (int ni = 0; ni < 4; ni++) {
                const int c0i = wn + ni * 8 + gid;
                uint2 bb = *(const uint2*)&Bs[c0i * GPAD + kk];
#pragma unroll
                for (int mi = 0; mi < 4; mi++)
                    mma_tf32(acc[mi][ni], af[mi], bb.x, bb.y);
            }
        }

        if (more) {
#pragma unroll
            for (int i = 0; i < 4; i++) {
                uint32_t* bs = &Bsn[(lr + i * 32) * GPAD + sp];
                bs[0] = f2tf(rb[i].x); bs[2] = f2tf(rb[i].y);
                bs[4] = f2tf(rb[i].z); bs[6] = f2tf(rb[i].w);
            }
        }
        __syncthreads();
    }

    // CTA-level output routing (region boundaries are 128-aligned)
    float* dst; int coff, ld;
    if (n0 < nc0)            { dst = c0; coff = n0;             ld = ld0; }
    else if (n0 < nc0 + nc1) { dst = c1; coff = n0 - nc0;       ld = ld1; }
    else                     { dst = c2; coff = n0 - nc0 - nc1; ld = ld2; }

#pragma unroll
    for (int mi = 0; mi < 4; mi++) {
        const int r0 = m0 + wm + mi * 16 + gid;
#pragma unroll
        for (int ni = 0; ni < 4; ni++) {
            const int c = coff + wn + ni * 8 + tig * 2;
            *(float2*)&dst[(size_t)r0 * ld + c] =
                make_float2(acc[mi][ni][0], acc[mi][ni][1]);
            *(float2*)&dst[(size_t)(r0 + 8) * ld + c] =
                make_float2(acc[mi][ni][2], acc[mi][ni][3]);
        }
    }
}

// ---------------- RoPE ----------------------------------------------------
__global__ __launch_bounds__(256) void rope_kernel(
    float* __restrict__ q, float* __restrict__ k)
{
    const int t = blockIdx.x;
    const int idx = blockIdx.y * 256 + threadIdx.x;
    const int head = idx >> 6;
    const int d = idx & 63;

    const float invf = exp2f((float)d * (-13.287712379549449f / 64.0f));
    float fr = (float)t * invf;
    float c = cosf(fr), s = sinf(fr);

    float* base;
    if (head < 16) base = q + ((size_t)t * 16 + head) * 128;
    else           base = k + ((size_t)t * 4 + (head - 16)) * 128;

    float x1 = base[d];
    float x2 = base[d + 64];
    base[d]      = x1 * c - x2 * s;
    base[d + 64] = x1 * s + x2 * c;
}

// =============== tensor-core flash attention (unchanged, R6) ==============
#define KSTR 132
#define PSTR 36

__global__ __launch_bounds__(256) void attn_mma(
    const float* __restrict__ q, const float* __restrict__ k,
    const float* __restrict__ v, float* __restrict__ out)
{
    __shared__ uint32_t KP[4608];
    __shared__ uint32_t Vs[32 * KSTR];

    const int t0   = blockIdx.x * 32;
    const int gh   = blockIdx.y;
    const int tid  = threadIdx.x;
    const int warp = tid >> 5;
    const int lane = tid & 31;
    const int g    = lane >> 2;
    const int tig  = lane & 3;
    const float scale = 0.08838834764831845f;

    const int mA = warp * 16 + g;
    const int mB = mA + 8;
    const int tA = t0 + (mA & 31), tB = t0 + (mB & 31);
    const int hA = gh * 4 + (mA >> 5), hB = gh * 4 + (mB >> 5);

    uint32_t qa[16][4];
    const float* qAp = q + ((size_t)tA * 16 + hA) * 128;
    const float* qBp = q + ((size_t)tB * 16 + hB) * 128;
#pragma unroll
    for (int ks = 0; ks < 16; ks++) {
        qa[ks][0] = f2tf(qAp[8 * ks + tig]);
        qa[ks][1] = f2tf(qBp[8 * ks + tig]);
        qa[ks][2] = f2tf(qAp[8 * ks + tig + 4]);
        qa[ks][3] = f2tf(qBp[8 * ks + tig + 4]);
    }

    float oa[16][4];
#pragma unroll
    for (int i = 0; i < 16; i++)
#pragma unroll
        for (int r = 0; r < 4; r++) oa[i][r] = 0.0f;
    float rmA = -1e30f, rmB = -1e30f, rlA = 0.0f, rlB = 0.0f;

    uint32_t* Pw = &KP[warp * 16 * PSTR];

    for (int c = 0; c < 17; c++) {
        const int sb = t0 - 512 + 32 * c;
        if (sb + 31 < 0) continue;

#pragma unroll
        for (int i = 0; i < 4; i++) {
            int idx = tid + 256 * i;
            int row = idx >> 5;
            int c4  = (idx & 31) * 4;
            int s = sb + row;
            float4 k4 = make_float4(0.f, 0.f, 0.f, 0.f);
            float4 v4 = make_float4(0.f, 0.f, 0.f, 0.f);
            if (s >= 0) {
                k4 = *(const float4*)&k[((size_t)s * 4 + gh) * 128 + c4];
                v4 = *(const float4*)&v[((size_t)s * 4 + gh) * 128 + c4];
            }
            uint4 kp = make_uint4(f2tf(k4.x), f2tf(k4.y), f2tf(k4.z), f2tf(k4.w));
            uint4 vp = make_uint4(f2tf(v4.x), f2tf(v4.y), f2tf(v4.z), f2tf(v4.w));
            *(uint4*)&KP[row * KSTR + c4] = kp;
            *(uint4*)&Vs[row * KSTR + c4] = vp;
        }
        __syncthreads();

        float sf[4][4];
#pragma unroll
        for (int ni = 0; ni < 4; ni++)
#pragma unroll
            for (int r = 0; r < 4; r++) sf[ni][r] = 0.0f;
#pragma unroll
        for (int ks = 0; ks < 16; ks++) {
            const int kk = ks * 8;
#pragma unroll
            for (int ni = 0; ni < 4; ni++) {
                uint32_t b0 = KP[(ni * 8 + g) * KSTR + kk + tig];
                uint32_t b1 = KP[(ni * 8 + g) * KSTR + kk + tig + 4];
                mma_tf32(sf[ni], qa[ks], b0, b1);
            }
        }
        __syncthreads();

        float cmA = -1e30f, cmB = -1e30f;
#pragma unroll
        for (int ni = 0; ni < 4; ni++) {
#pragma unroll
            for (int jj = 0; jj < 2; jj++) {
                const int s = sb + ni * 8 + tig * 2 + jj;
                bool okA = (s >= 0) && (s <= tA) && (tA - s <= 512);
                bool okB = (s >= 0) && (s <= tB) && (tB - s <= 512);
                sf[ni][jj]     = okA ? sf[ni][jj]     * scale : -1e30f;
                sf[ni][2 + jj] = okB ? sf[ni][2 + jj] * scale : -1e30f;
                cmA = fmaxf(cmA, sf[ni][jj]);
                cmB = fmaxf(cmB, sf[ni][2 + jj]);
            }
        }
        cmA = fmaxf(cmA, __shfl_xor_sync(0xffffffffu, cmA, 1));
        cmA = fmaxf(cmA, __shfl_xor_sync(0xffffffffu, cmA, 2));
        cmB = fmaxf(cmB, __shfl_xor_sync(0xffffffffu, cmB, 1));
        cmB = fmaxf(cmB, __shfl_xor_sync(0xffffffffu, cmB, 2));

        const float nmA = fmaxf(rmA, cmA), nmB = fmaxf(rmB, cmB);
        const float alA = __expf(rmA - nmA), alB = __expf(rmB - nmB);
        rmA = nmA; rmB = nmB;

        float clA = 0.f, clB = 0.f;
#pragma unroll
        for (int ni = 0; ni < 4; ni++) {
            float p0 = __expf(sf[ni][0] - nmA);
            float p1 = __expf(sf[ni][1] - nmA);
            float p2 = __expf(sf[ni][2] - nmB);
            float p3 = __expf(sf[ni][3] - nmB);
            clA += p0 + p1; clB += p2 + p3;
            const int col = ni * 8 + tig * 2;
            Pw[g * PSTR + col]           = f2tf(p0);
            Pw[g * PSTR + col + 1]       = f2tf(p1);
            Pw[(g + 8) * PSTR + col]     = f2tf(p2);
            Pw[(g + 8) * PSTR + col + 1] = f2tf(p3);
        }
        clA += __shfl_xor_sync(0xffffffffu, clA, 1);
        clA += __shfl_xor_sync(0xffffffffu, clA, 2);
        clB += __shfl_xor_sync(0xffffffffu, clB, 1);
        clB += __shfl_xor_sync(0xffffffffu, clB, 2);
        rlA = rlA * alA + clA;
        rlB = rlB * alB + clB;

#pragma unroll
        for (int ni2 = 0; ni2 < 16; ni2++) {
            oa[ni2][0] *= alA; oa[ni2][1] *= alA;
            oa[ni2][2] *= alB; oa[ni2][3] *= alB;
        }
        __syncwarp();

#pragma unroll
        for (int ks = 0; ks < 4; ks++) {
            const int kk = ks * 8;
            uint32_t pa[4];
            pa[0] = Pw[g * PSTR + kk + tig];
            pa[1] = Pw[(g + 8) * PSTR + kk + tig];
            pa[2] = Pw[g * PSTR + kk + tig + 4];
            pa[3] = Pw[(g + 8) * PSTR + kk + tig + 4];
#pragma unroll
            for (int ni2 = 0; ni2 < 16; ni2++) {
                uint32_t b0 = Vs[(kk + tig) * KSTR + ni2 * 8 + g];
                uint32_t b1 = Vs[(kk + tig + 4) * KSTR + ni2 * 8 + g];
                mma_tf32(oa[ni2], pa, b0, b1);
            }
        }
        __syncthreads();
    }

    const float ilA = 1.0f / rlA, ilB = 1.0f / rlB;
    float* oAp = out + ((size_t)tA * 16 + hA) * 128;
    float* oBp = out + ((size_t)tB * 16 + hB) * 128;
#pragma unroll
    for (int ni2 = 0; ni2 < 16; ni2++) {
        const int d0 = ni2 * 8 + tig * 2;
        *(float2*)&oAp[d0] = make_float2(oa[ni2][0] * ilA, oa[ni2][1] * ilA);
        *(float2*)&oBp[d0] = make_float2(oa[ni2][2] * ilB, oa[ni2][3] * ilB);
    }
}

// ---------------- launcher -------------------------------------------------
extern "C" void kernel_launch(void* const* d_in, const int* in_sizes, int n_in,
                              void* d_out, int out_size)
{
    const float* x  = (const float*)d_in[0];
    const float* wq = (const float*)d_in[1];
    const float* wk = (const float*)d_in[2];
    const float* wv = (const float*)d_in[3];
    const float* wo = (const float*)d_in[4];
    float* out = (float*)d_out;

    float *q, *k, *v, *att, *wcat;
    cudaGetSymbolAddress((void**)&q,    g_q);
    cudaGetSymbolAddress((void**)&k,    g_k);
    cudaGetSymbolAddress((void**)&v,    g_v);
    cudaGetSymbolAddress((void**)&att,  g_att);
    cudaGetSymbolAddress((void**)&wcat, g_wcat);

    cudaFuncSetAttribute(gemm_db, cudaFuncAttributeMaxDynamicSharedMemorySize,
                         GEMM_SMEM);

    // concatenate [wq; wk; wv] (D2D, graph-capturable)
    cudaMemcpyAsync(wcat,                wq, (size_t)2048 * 2048 * 4,
                    cudaMemcpyDeviceToDevice);
    cudaMemcpyAsync(wcat + 2048 * 2048,  wk, (size_t)512 * 2048 * 4,
                    cudaMemcpyDeviceToDevice);
    cudaMemcpyAsync(wcat + 2560 * 2048,  wv, (size_t)512 * 2048 * 4,
                    cudaMemcpyDeviceToDevice);

    // fused QKV projection
    gemm_db<<<dim3(24, 32), 256, GEMM_SMEM>>>(x, wcat,
                                              q, 2048, 2048,
                                              k, 512, 512,
                                              v, 512, 2048);

    rope_kernel<<<dim3(TLEN, 5), 256>>>(q, k);

    attn_mma<<<dim3(TLEN / 32, 4), 256>>>(q, k, v, att);

    // output projection
    gemm_db<<<dim3(16, 32), 256, GEMM_SMEM>>>(att, wo,
                                              out, 2048, 2048,
                                              out, 0, 2048,
                                              out, 2048, 2048);
}

// round 14
// speedup vs baseline: 1.2752x; 1.2752x over previous
#include <cuda_runtime.h>
#include <math.h>
#include <stdint.h>

// ---------------- scratch (device globals; no allocation allowed) ----------
#define TLEN 4096
__device__ float g_q[TLEN * 2048];
__device__ float g_k[TLEN * 512];
__device__ float g_v[TLEN * 512];
__device__ float g_att[TLEN * 2048];
// tf32 pre-converted GEMM operands
__device__ uint32_t g_xt[TLEN * 2048];
__device__ uint32_t g_wt[3072 * 2048];   // [wq;wk;wv] tf32
__device__ uint32_t g_ot[2048 * 2048];   // wo tf32
__device__ uint32_t g_at[TLEN * 2048];   // att tf32

__device__ __forceinline__ uint32_t f2tf(float x) {
    uint32_t r;
    asm("cvt.rna.tf32.f32 %0, %1;" : "=r"(r) : "f"(x));
    return r;
}
__device__ __forceinline__ void mma_tf32(float c[4], const uint32_t a[4],
                                         const uint32_t b0, const uint32_t b1) {
    asm volatile(
        "mma.sync.aligned.m16n8k8.row.col.f32.tf32.tf32.f32 "
        "{%0,%1,%2,%3},{%4,%5,%6,%7},{%8,%9},{%0,%1,%2,%3};\n"
        : "+f"(c[0]), "+f"(c[1]), "+f"(c[2]), "+f"(c[3])
        : "r"(a[0]), "r"(a[1]), "r"(a[2]), "r"(a[3]), "r"(b0), "r"(b1));
}
__device__ __forceinline__ void cp16(uint32_t saddr, const void* gptr) {
    asm volatile("cp.async.ca.shared.global [%0], [%1], 16;\n"
                 :: "r"(saddr), "l"(gptr));
}

// ---------------- fp32 -> tf32 conversion ---------------------------------
__global__ __launch_bounds__(256) void conv_tf32(
    const float* __restrict__ src, uint32_t* __restrict__ dst, int n)
{
    int i = (blockIdx.x * 256 + threadIdx.x) * 4;
    if (i >= n) return;
    float4 x = *(const float4*)(src + i);
    *(uint4*)(dst + i) = make_uint4(f2tf(x.x), f2tf(x.y), f2tf(x.z), f2tf(x.w));
}

// ====== cp.async 3-stage TF32 GEMM: C[M,N] = A[M,K] * B[N,K]^T ============
// A, B pre-converted tf32. Tile 128x128x32, 256 thr, warp tile 64x32.
// 3 smem stages x (As[128][36] + Bs[128][36]); LDGSTS only, no staging.
#define GPAD 36
#define STGW 9216          // words per stage
#define GEMM_SMEM 110592   // 3 stages

__global__ __launch_bounds__(256, 2) void gemm_cp(
    const uint32_t* __restrict__ A, const uint32_t* __restrict__ B,
    float* __restrict__ c0, int nc0, int ld0,
    float* __restrict__ c1, int nc1, int ld1,
    float* __restrict__ c2, int ld2, int K)
{
    extern __shared__ uint32_t sm[];
    const uint32_t sbase = (uint32_t)__cvta_generic_to_shared(sm);

    const int tid  = threadIdx.x;
    const int warp = tid >> 5;
    const int lane = tid & 31;
    const int gid  = lane >> 2;
    const int tig  = lane & 3;
    const int wm   = (warp >> 2) * 64;
    const int wn   = (warp & 3) * 32;
    const int m0   = blockIdx.y * 128;
    const int n0   = blockIdx.x * 128;

    const int lr = tid >> 3;         // 0..31
    const int lk = (tid & 7) * 4;    // 0..28

    float acc[4][4][4];
#pragma unroll
    for (int mi = 0; mi < 4; mi++)
#pragma unroll
        for (int ni = 0; ni < 4; ni++)
#pragma unroll
            for (int r = 0; r < 4; r++) acc[mi][ni][r] = 0.0f;

    const uint32_t* Ap = A + (size_t)(m0 + lr) * K + lk;
    const uint32_t* Bp = B + (size_t)(n0 + lr) * K + lk;
    const int NT = K >> 5;

    // issue one stage's loads (8 x 16B per thread)
    auto issue = [&](int kt) {
        const int buf = kt % 3;
        const uint32_t sa = sbase + (buf * STGW + lr * GPAD + lk) * 4;
        const uint32_t sb = sa + 4608 * 4;
        const uint32_t* ap = Ap + kt * 32;
        const uint32_t* bp = Bp + kt * 32;
#pragma unroll
        for (int i = 0; i < 4; i++) {
            cp16(sa + i * 32 * GPAD * 4, ap + (size_t)i * 32 * K);
            cp16(sb + i * 32 * GPAD * 4, bp + (size_t)i * 32 * K);
        }
    };

    issue(0);
    asm volatile("cp.async.commit_group;\n");
    if (NT > 1) issue(1);
    asm volatile("cp.async.commit_group;\n");

    for (int kt = 0; kt < NT; kt++) {
        asm volatile("cp.async.wait_group 1;\n");
        __syncthreads();

        if (kt + 2 < NT) issue(kt + 2);
        asm volatile("cp.async.commit_group;\n");

        const uint32_t* As = sm + (kt % 3) * STGW;
        const uint32_t* Bs = As + 4608;

#pragma unroll
        for (int ks = 0; ks < 4; ks++) {
            const int kk = ks * 8;
            uint32_t af[4][4];
#pragma unroll
            for (int mi = 0; mi < 4; mi++) {
                const int r0 = wm + mi * 16 + gid;
                af[mi][0] = As[(r0    ) * GPAD + kk + tig];
                af[mi][1] = As[(r0 + 8) * GPAD + kk + tig];
                af[mi][2] = As[(r0    ) * GPAD + kk + tig + 4];
                af[mi][3] = As[(r0 + 8) * GPAD + kk + tig + 4];
            }
#pragma unroll
            for (int ni = 0; ni < 4; ni++) {
                const int c0i = wn + ni * 8 + gid;
                uint32_t b0 = Bs[c0i * GPAD + kk + tig];
                uint32_t b1 = Bs[c0i * GPAD + kk + tig + 4];
#pragma unroll
                for (int mi = 0; mi < 4; mi++)
                    mma_tf32(acc[mi][ni], af[mi], b0, b1);
            }
        }
        __syncthreads();
    }

    // CTA-level output routing (region boundaries are 128-aligned)
    float* dst; int coff, ld;
    if (n0 < nc0)            { dst = c0; coff = n0;             ld = ld0; }
    else if (n0 < nc0 + nc1) { dst = c1; coff = n0 - nc0;       ld = ld1; }
    else                     { dst = c2; coff = n0 - nc0 - nc1; ld = ld2; }

#pragma unroll
    for (int mi = 0; mi < 4; mi++) {
        const int r0 = m0 + wm + mi * 16 + gid;
#pragma unroll
        for (int ni = 0; ni < 4; ni++) {
            const int c = coff + wn + ni * 8 + tig * 2;
            *(float2*)&dst[(size_t)r0 * ld + c] =
                make_float2(acc[mi][ni][0], acc[mi][ni][1]);
            *(float2*)&dst[(size_t)(r0 + 8) * ld + c] =
                make_float2(acc[mi][ni][2], acc[mi][ni][3]);
        }
    }
}

// ---------------- RoPE ----------------------------------------------------
__global__ __launch_bounds__(256) void rope_kernel(
    float* __restrict__ q, float* __restrict__ k)
{
    const int t = blockIdx.x;
    const int idx = blockIdx.y * 256 + threadIdx.x;
    const int head = idx >> 6;
    const int d = idx & 63;

    const float invf = exp2f((float)d * (-13.287712379549449f / 64.0f));
    float fr = (float)t * invf;
    float c = cosf(fr), s = sinf(fr);

    float* base;
    if (head < 16) base = q + ((size_t)t * 16 + head) * 128;
    else           base = k + ((size_t)t * 4 + (head - 16)) * 128;

    float x1 = base[d];
    float x2 = base[d + 64];
    base[d]      = x1 * c - x2 * s;
    base[d + 64] = x1 * s + x2 * c;
}

// =============== tensor-core flash attention (unchanged, R6) ==============
#define KSTR 132
#define PSTR 36

__global__ __launch_bounds__(256) void attn_mma(
    const float* __restrict__ q, const float* __restrict__ k,
    const float* __restrict__ v, float* __restrict__ out)
{
    __shared__ uint32_t KP[4608];
    __shared__ uint32_t Vs[32 * KSTR];

    const int t0   = blockIdx.x * 32;
    const int gh   = blockIdx.y;
    const int tid  = threadIdx.x;
    const int warp = tid >> 5;
    const int lane = tid & 31;
    const int g    = lane >> 2;
    const int tig  = lane & 3;
    const float scale = 0.08838834764831845f;

    const int mA = warp * 16 + g;
    const int mB = mA + 8;
    const int tA = t0 + (mA & 31), tB = t0 + (mB & 31);
    const int hA = gh * 4 + (mA >> 5), hB = gh * 4 + (mB >> 5);

    uint32_t qa[16][4];
    const float* qAp = q + ((size_t)tA * 16 + hA) * 128;
    const float* qBp = q + ((size_t)tB * 16 + hB) * 128;
#pragma unroll
    for (int ks = 0; ks < 16; ks++) {
        qa[ks][0] = f2tf(qAp[8 * ks + tig]);
        qa[ks][1] = f2tf(qBp[8 * ks + tig]);
        qa[ks][2] = f2tf(qAp[8 * ks + tig + 4]);
        qa[ks][3] = f2tf(qBp[8 * ks + tig + 4]);
    }

    float oa[16][4];
#pragma unroll
    for (int i = 0; i < 16; i++)
#pragma unroll
        for (int r = 0; r < 4; r++) oa[i][r] = 0.0f;
    float rmA = -1e30f, rmB = -1e30f, rlA = 0.0f, rlB = 0.0f;

    uint32_t* Pw = &KP[warp * 16 * PSTR];

    for (int c = 0; c < 17; c++) {
        const int sb = t0 - 512 + 32 * c;
        if (sb + 31 < 0) continue;

#pragma unroll
        for (int i = 0; i < 4; i++) {
            int idx = tid + 256 * i;
            int row = idx >> 5;
            int c4  = (idx & 31) * 4;
            int s = sb + row;
            float4 k4 = make_float4(0.f, 0.f, 0.f, 0.f);
            float4 v4 = make_float4(0.f, 0.f, 0.f, 0.f);
            if (s >= 0) {
                k4 = *(const float4*)&k[((size_t)s * 4 + gh) * 128 + c4];
                v4 = *(const float4*)&v[((size_t)s * 4 + gh) * 128 + c4];
            }
            uint4 kp = make_uint4(f2tf(k4.x), f2tf(k4.y), f2tf(k4.z), f2tf(k4.w));
            uint4 vp = make_uint4(f2tf(v4.x), f2tf(v4.y), f2tf(v4.z), f2tf(v4.w));
            *(uint4*)&KP[row * KSTR + c4] = kp;
            *(uint4*)&Vs[row * KSTR + c4] = vp;
        }
        __syncthreads();

        float sf[4][4];
#pragma unroll
        for (int ni = 0; ni < 4; ni++)
#pragma unroll
            for (int r = 0; r < 4; r++) sf[ni][r] = 0.0f;
#pragma unroll
        for (int ks = 0; ks < 16; ks++) {
            const int kk = ks * 8;
#pragma unroll
            for (int ni = 0; ni < 4; ni++) {
                uint32_t b0 = KP[(ni * 8 + g) * KSTR + kk + tig];
                uint32_t b1 = KP[(ni * 8 + g) * KSTR + kk + tig + 4];
                mma_tf32(sf[ni], qa[ks], b0, b1);
            }
        }
        __syncthreads();

        float cmA = -1e30f, cmB = -1e30f;
#pragma unroll
        for (int ni = 0; ni < 4; ni++) {
#pragma unroll
            for (int jj = 0; jj < 2; jj++) {
                const int s = sb + ni * 8 + tig * 2 + jj;
                bool okA = (s >= 0) && (s <= tA) && (tA - s <= 512);
                bool okB = (s >= 0) && (s <= tB) && (tB - s <= 512);
                sf[ni][jj]     = okA ? sf[ni][jj]     * scale : -1e30f;
                sf[ni][2 + jj] = okB ? sf[ni][2 + jj] * scale : -1e30f;
                cmA = fmaxf(cmA, sf[ni][jj]);
                cmB = fmaxf(cmB, sf[ni][2 + jj]);
            }
        }
        cmA = fmaxf(cmA, __shfl_xor_sync(0xffffffffu, cmA, 1));
        cmA = fmaxf(cmA, __shfl_xor_sync(0xffffffffu, cmA, 2));
        cmB = fmaxf(cmB, __shfl_xor_sync(0xffffffffu, cmB, 1));
        cmB = fmaxf(cmB, __shfl_xor_sync(0xffffffffu, cmB, 2));

        const float nmA = fmaxf(rmA, cmA), nmB = fmaxf(rmB, cmB);
        const float alA = __expf(rmA - nmA), alB = __expf(rmB - nmB);
        rmA = nmA; rmB = nmB;

        float clA = 0.f, clB = 0.f;
#pragma unroll
        for (int ni = 0; ni < 4; ni++) {
            float p0 = __expf(sf[ni][0] - nmA);
            float p1 = __expf(sf[ni][1] - nmA);
            float p2 = __expf(sf[ni][2] - nmB);
            float p3 = __expf(sf[ni][3] - nmB);
            clA += p0 + p1; clB += p2 + p3;
            const int col = ni * 8 + tig * 2;
            Pw[g * PSTR + col]           = f2tf(p0);
            Pw[g * PSTR + col + 1]       = f2tf(p1);
            Pw[(g + 8) * PSTR + col]     = f2tf(p2);
            Pw[(g + 8) * PSTR + col + 1] = f2tf(p3);
        }
        clA += __shfl_xor_sync(0xffffffffu, clA, 1);
        clA += __shfl_xor_sync(0xffffffffu, clA, 2);
        clB += __shfl_xor_sync(0xffffffffu, clB, 1);
        clB += __shfl_xor_sync(0xffffffffu, clB, 2);
        rlA = rlA * alA + clA;
        rlB = rlB * alB + clB;

#pragma unroll
        for (int ni2 = 0; ni2 < 16; ni2++) {
            oa[ni2][0] *= alA; oa[ni2][1] *= alA;
            oa[ni2][2] *= alB; oa[ni2][3] *= alB;
        }
        __syncwarp();

#pragma unroll
        for (int ks = 0; ks < 4; ks++) {
            const int kk = ks * 8;
            uint32_t pa[4];
            pa[0] = Pw[g * PSTR + kk + tig];
            pa[1] = Pw[(g + 8) * PSTR + kk + tig];
            pa[2] = Pw[g * PSTR + kk + tig + 4];
            pa[3] = Pw[(g + 8) * PSTR + kk + tig + 4];
#pragma unroll
            for (int ni2 = 0; ni2 < 16; ni2++) {
                uint32_t b0 = Vs[(kk + tig) * KSTR + ni2 * 8 + g];
                uint32_t b1 = Vs[(kk + tig + 4) * KSTR + ni2 * 8 + g];
                mma_tf32(oa[ni2], pa, b0, b1);
            }
        }
        __syncthreads();
    }

    const float ilA = 1.0f / rlA, ilB = 1.0f / rlB;
    float* oAp = out + ((size_t)tA * 16 + hA) * 128;
    float* oBp = out + ((size_t)tB * 16 + hB) * 128;
#pragma unroll
    for (int ni2 = 0; ni2 < 16; ni2++) {
        const int d0 = ni2 * 8 + tig * 2;
        *(float2*)&oAp[d0] = make_float2(oa[ni2][0] * ilA, oa[ni2][1] * ilA);
        *(float2*)&oBp[d0] = make_float2(oa[ni2][2] * ilB, oa[ni2][3] * ilB);
    }
}

// ---------------- launcher -------------------------------------------------
extern "C" void kernel_launch(void* const* d_in, const int* in_sizes, int n_in,
                              void* d_out, int out_size)
{
    const float* x  = (const float*)d_in[0];
    const float* wq = (const float*)d_in[1];
    const float* wk = (const float*)d_in[2];
    const float* wv = (const float*)d_in[3];
    const float* wo = (const float*)d_in[4];
    float* out = (float*)d_out;

    float *q, *k, *v, *att;
    uint32_t *xt, *wt, *ot, *at;
    cudaGetSymbolAddress((void**)&q,   g_q);
    cudaGetSymbolAddress((void**)&k,   g_k);
    cudaGetSymbolAddress((void**)&v,   g_v);
    cudaGetSymbolAddress((void**)&att, g_att);
    cudaGetSymbolAddress((void**)&xt,  g_xt);
    cudaGetSymbolAddress((void**)&wt,  g_wt);
    cudaGetSymbolAddress((void**)&ot,  g_ot);
    cudaGetSymbolAddress((void**)&at,  g_at);

    cudaFuncSetAttribute(gemm_cp, cudaFuncAttributeMaxDynamicSharedMemorySize,
                         GEMM_SMEM);

    // pre-convert all GEMM operands to tf32 (weights written concatenated)
    conv_tf32<<<8192, 256>>>(x,  xt, TLEN * 2048);
    conv_tf32<<<4096, 256>>>(wq, wt,              2048 * 2048);
    conv_tf32<<<1024, 256>>>(wk, wt + 2048 * 2048, 512 * 2048);
    conv_tf32<<<1024, 256>>>(wv, wt + 2560 * 2048, 512 * 2048);
    conv_tf32<<<4096, 256>>>(wo, ot, 2048 * 2048);

    // fused QKV projection
    gemm_cp<<<dim3(24, 32), 256, GEMM_SMEM>>>(xt, wt,
                                              q, 2048, 2048,
                                              k, 512, 512,
                                              v, 512, 2048);

    rope_kernel<<<dim3(TLEN, 5), 256>>>(q, k);

    attn_mma<<<dim3(TLEN / 32, 4), 256>>>(q, k, v, att);

    // output projection
    conv_tf32<<<8192, 256>>>(att, at, TLEN * 2048);
    gemm_cp<<<dim3(16, 32), 256, GEMM_SMEM>>>(at, ot,
                                              out, 2048, 2048,
                                              out, 0, 2048,
                                              out, 2048, 2048);
}